// round 16
// baseline (speedup 1.0000x reference)
#include <cuda_runtime.h>
#include <cstdint>
#include <math.h>

// ---------------- problem constants (fixed by setup_inputs) ----------------
#define NNODES 131072
#define NEDGE  2097152
#define HDIM   128
#define NGRAPH 128
#define NPG    1024
#define NTOK   8
#define NHEAD  4
#define HD     32
#define MI     256   // mamba intermediate
#define MS     16    // mamba state
#define MR     8     // dt rank
#define MK     4     // conv kernel

// ---------------- device scratch (no allocation allowed) -------------------
__device__ __align__(16) float g_xa  [NNODES*HDIM];
__device__ __align__(16) float g_xcur[NNODES*HDIM];
__device__ __align__(16) float g_xs  [NNODES*32];
__device__ __align__(16) float g_M   [2*HDIM*32];
__device__ __align__(16) float g_W2  [2*4*HDIM*HDIM];
__device__ __align__(16) float g_tb  [2*HDIM];
__device__ __align__(16) float g_tok [NGRAPH*NTOK*HDIM];
__device__ __align__(16) float g_gf  [NGRAPH*HDIM];
__device__ __align__(16) float g_S   [NGRAPH*HDIM];
__device__ int g_deg [NNODES];
__device__ int g_off [NNODES + 1];
__device__ int g_cur [NNODES];
__device__ int g_bsum[512];
__device__ int g_ssrc[NEDGE];

__device__ __forceinline__ unsigned long long dup2(float v) {
    unsigned long long r;
    asm("mov.b64 %0,{%1,%1};" : "=l"(r) : "f"(v));
    return r;
}

// ---------------- CSR build: histogram -> 3-phase scan -> scatter ----------
__global__ __launch_bounds__(256) void hist_kernel(
    const int2* __restrict__ eid, int E2, int* __restrict__ deg)
{
    int e = blockIdx.x * 256 + threadIdx.x;
    if (e < E2) {
        int2 d = eid[e];
        atomicAdd(&deg[d.x], 1);
        atomicAdd(&deg[d.y], 1);
    }
}

__global__ __launch_bounds__(256) void blocksum_kernel(
    const int* __restrict__ deg, int* __restrict__ bsum)
{
    __shared__ int sh[256];
    int t = threadIdx.x;
    sh[t] = deg[blockIdx.x * 256 + t];
    __syncthreads();
#pragma unroll
    for (int o = 128; o > 0; o >>= 1) {
        if (t < o) sh[t] += sh[t + o];
        __syncthreads();
    }
    if (t == 0) bsum[blockIdx.x] = sh[0];
}

__global__ __launch_bounds__(512) void scanb_kernel(int* __restrict__ bsum)
{
    __shared__ int sh[512];
    int t = threadIdx.x;
    int v = bsum[t];
    sh[t] = v;
    __syncthreads();
    for (int o = 1; o < 512; o <<= 1) {
        int u = (t >= o) ? sh[t - o] : 0;
        __syncthreads();
        sh[t] += u;
        __syncthreads();
    }
    bsum[t] = sh[t] - v;
}

__global__ __launch_bounds__(256) void offsets_kernel(
    const int* __restrict__ deg, const int* __restrict__ bsum,
    int* __restrict__ off, int* __restrict__ cur)
{
    __shared__ int sh[256];
    int t = threadIdx.x;
    int base = blockIdx.x * 256;
    int d = deg[base + t];
    sh[t] = d;
    __syncthreads();
    for (int o = 1; o < 256; o <<= 1) {
        int u = (t >= o) ? sh[t - o] : 0;
        __syncthreads();
        sh[t] += u;
        __syncthreads();
    }
    int o_excl = bsum[blockIdx.x] + sh[t] - d;
    off[base + t] = o_excl;
    cur[base + t] = o_excl;
    if (blockIdx.x == 511 && t == 255) off[NNODES] = bsum[511] + sh[255];
}

__global__ __launch_bounds__(256) void scatter_kernel(
    const int2* __restrict__ eis, const int2* __restrict__ eid, int E2,
    int* __restrict__ cur, int* __restrict__ ssrc)
{
    int e = blockIdx.x * 256 + threadIdx.x;
    if (e >= E2) return;
    int2 s = eis[e];
    int2 d = eid[e];
    ssrc[atomicAdd(&cur[d.x], 1)] = s.x;
    ssrc[atomicAdd(&cur[d.y], 1)] = s.y;
}

// ---------------- gather helper: acc = x[nd] + sum_{src} x[src] ------------
__device__ __forceinline__ float4 gather_row(
    const float* __restrict__ x, const int* __restrict__ off,
    const int* __restrict__ ssrc, int nd, int lane)
{
    int s = off[nd], e = off[nd + 1];
    float4 acc = *(const float4*)(x + (size_t)nd * HDIM + lane * 4);
    int i = s;
    int n8 = s + ((e - s) & ~7);
    for (; i < n8; i += 8) {
        int id[8];
#pragma unroll
        for (int j = 0; j < 8; j++) id[j] = __ldg(&ssrc[i + j]);
        float4 v[8];
#pragma unroll
        for (int j = 0; j < 8; j++)
            v[j] = *(const float4*)(x + (size_t)id[j] * HDIM + lane * 4);
#pragma unroll
        for (int j = 0; j < 8; j++) {
            acc.x += v[j].x; acc.y += v[j].y; acc.z += v[j].z; acc.w += v[j].w;
        }
    }
    for (; i < e; i++) {
        int s0 = __ldg(&ssrc[i]);
        float4 v = *(const float4*)(x + (size_t)s0 * HDIM + lane * 4);
        acc.x += v.x; acc.y += v.y; acc.z += v.z; acc.w += v.w;
    }
    return acc;
}

__global__ __launch_bounds__(256) void csr_agg_kernel(
    const float* __restrict__ x, int nbase, const int* __restrict__ off,
    const int* __restrict__ ssrc, float* __restrict__ xa)
{
    int nd = nbase + blockIdx.x * 8 + (threadIdx.x >> 5);
    int lane = threadIdx.x & 31;
    float4 acc = gather_row(x, off, ssrc, nd, lane);
    *(float4*)(xa + (size_t)nd * HDIM + lane * 4) = acc;
}

__global__ __launch_bounds__(256) void csr_sum_kernel(
    const float* __restrict__ x, const int* __restrict__ off,
    const int* __restrict__ ssrc, float* __restrict__ S)
{
    __shared__ float sh[8][HDIM];
    int w = threadIdx.x >> 5, lane = threadIdx.x & 31;
    int nd = blockIdx.x * 8 + w;
    float4 acc = gather_row(x, off, ssrc, nd, lane);
    *(float4*)&sh[w][lane * 4] = acc;
    __syncthreads();
    if (threadIdx.x < 32) {
        float4 t = make_float4(0.f, 0.f, 0.f, 0.f);
#pragma unroll
        for (int r = 0; r < 8; r++) {
            float4 v = *(const float4*)&sh[r][threadIdx.x * 4];
            t.x += v.x; t.y += v.y; t.z += v.z; t.w += v.w;
        }
        int g = (blockIdx.x * 8) >> 10;
        float* ap = S + g * HDIM + threadIdx.x * 4;
        asm volatile("red.global.add.v4.f32 [%0], {%1,%2,%3,%4};"
                     :: "l"(ap), "f"(t.x), "f"(t.y), "f"(t.z), "f"(t.w) : "memory");
    }
}

// ---------------- GEMM: C = A @ W + bs*bias [+ gf] [+ fused xs = C @ M] ----
// 512 threads, 8x4 thread tile (acc = 32 regs -> no spill), full W in smem,
// double-buffered A chunks with register prefetch.
#define GEMM_SMEM (128*132*4 + 2*32*132*4)
__global__ __launch_bounds__(512, 1) void gemm_t(
    const float* __restrict__ A, int rbase,
    const float* __restrict__ W, int ldw,
    const float* __restrict__ bias, float bias_scale,
    const float* __restrict__ gf,
    float* __restrict__ C,
    const float* __restrict__ Mmat, float* __restrict__ xs)
{
    extern __shared__ char gsm[];
    float (*Wf)[132]     = (float(*)[132])gsm;                       // [k][col]
    float (*As)[32][132] = (float(*)[32][132])(gsm + 128 * 132 * 4); // [buf][k][row]
    int tid = threadIdx.x;
    int row0 = rbase + blockIdx.x * 128;
    int tx = tid & 31, ty = tid >> 5;    // col group (4 cols), row group (8 rows)

    // load full W (coalesced)
#pragma unroll
    for (int it = 0; it < 8; it++) {
        int lin = tid + it * 512;
        int k = lin >> 5, c4 = lin & 31;
        *(float4*)&Wf[k][c4 * 4] = *(const float4*)(W + (size_t)k * ldw + c4 * 4);
    }

    // prefetch chunk 0 (2 float4 per thread)
    float4 areg[2];
#pragma unroll
    for (int it = 0; it < 2; it++) {
        int lin = tid + it * 512;
        int row = lin >> 3, c4 = lin & 7;
        areg[it] = *(const float4*)(A + (size_t)(row0 + row) * HDIM + c4 * 4);
    }
#pragma unroll
    for (int it = 0; it < 2; it++) {
        int lin = tid + it * 512;
        int row = lin >> 3, c4 = lin & 7;
        As[0][c4 * 4 + 0][row] = areg[it].x;
        As[0][c4 * 4 + 1][row] = areg[it].y;
        As[0][c4 * 4 + 2][row] = areg[it].z;
        As[0][c4 * 4 + 3][row] = areg[it].w;
    }
    __syncthreads();

    unsigned long long acc[4][4];
#pragma unroll
    for (int i = 0; i < 4; i++)
#pragma unroll
        for (int j = 0; j < 4; j++) acc[i][j] = 0ull;

#pragma unroll
    for (int c = 0; c < 4; c++) {
        if (c < 3) {
#pragma unroll
            for (int it = 0; it < 2; it++) {
                int lin = tid + it * 512;
                int row = lin >> 3, c4 = lin & 7;
                areg[it] = *(const float4*)(A + (size_t)(row0 + row) * HDIM
                                            + (c + 1) * 32 + c4 * 4);
            }
        }
        int buf = c & 1;
#pragma unroll
        for (int kk = 0; kk < 32; kk++) {
            int kg = c * 32 + kk;
            ulonglong2 a01 = *(const ulonglong2*)&As[buf][kk][ty * 8];
            ulonglong2 a23 = *(const ulonglong2*)&As[buf][kk][ty * 8 + 4];
            float4 w = *(const float4*)&Wf[kg][tx * 4];
            unsigned long long ap[4] = {a01.x, a01.y, a23.x, a23.y};
            unsigned long long wd[4] = {dup2(w.x), dup2(w.y), dup2(w.z), dup2(w.w)};
#pragma unroll
            for (int i = 0; i < 4; i++)
#pragma unroll
                for (int j = 0; j < 4; j++)
                    asm("fma.rn.f32x2 %0, %1, %2, %0;"
                        : "+l"(acc[i][j]) : "l"(ap[i]), "l"(wd[j]));
        }
        if (c < 3) {
            __syncthreads();
            int nbuf = (c + 1) & 1;
#pragma unroll
            for (int it = 0; it < 2; it++) {
                int lin = tid + it * 512;
                int row = lin >> 3, c4 = lin & 7;
                As[nbuf][c4 * 4 + 0][row] = areg[it].x;
                As[nbuf][c4 * 4 + 1][row] = areg[it].y;
                As[nbuf][c4 * 4 + 2][row] = areg[it].z;
                As[nbuf][c4 * 4 + 3][row] = areg[it].w;
            }
            __syncthreads();
        }
    }

    int jc0 = tx * 4;
    float bj[4];
#pragma unroll
    for (int j = 0; j < 4; j++)
        bj[j] = bias ? bias_scale * bias[jc0 + j] : 0.f;
    if (gf) {
        int grp = row0 >> 10;
#pragma unroll
        for (int j = 0; j < 4; j++) bj[j] += gf[grp * HDIM + jc0 + j];
    }
#pragma unroll
    for (int i = 0; i < 4; i++) {
        int rlo = row0 + ty * 8 + 2 * i;
        float lo[4], hi[4];
#pragma unroll
        for (int j = 0; j < 4; j++)
            asm("mov.b64 {%0,%1}, %2;" : "=f"(lo[j]), "=f"(hi[j]) : "l"(acc[i][j]));
        *(float4*)(C + (size_t)rlo * HDIM + jc0) =
            make_float4(lo[0] + bj[0], lo[1] + bj[1], lo[2] + bj[2], lo[3] + bj[3]);
        *(float4*)(C + (size_t)(rlo + 1) * HDIM + jc0) =
            make_float4(hi[0] + bj[0], hi[1] + bj[1], hi[2] + bj[2], hi[3] + bj[3]);
    }

    if (!xs) return;

    // ---- fused scores epilogue: xs(block rows) = C_tile @ M ----
    __syncthreads();
    float (*Ct)[132] = Wf;
    float (*Ms)[32]  = (float(*)[32])&As[0][0][0];
#pragma unroll
    for (int i = 0; i < 4; i++) {
        int rl = ty * 8 + 2 * i;
        float lo[4], hi[4];
#pragma unroll
        for (int j = 0; j < 4; j++)
            asm("mov.b64 {%0,%1}, %2;" : "=f"(lo[j]), "=f"(hi[j]) : "l"(acc[i][j]));
#pragma unroll
        for (int j = 0; j < 4; j++) {
            Ct[rl][jc0 + j]     = lo[j] + bj[j];
            Ct[rl + 1][jc0 + j] = hi[j] + bj[j];
        }
    }
#pragma unroll
    for (int it = 0; it < 2; it++) {
        int lin = tid + it * 512;
        int k = lin >> 3, c4 = lin & 7;
        *(float4*)&Ms[k][c4 * 4] = *(const float4*)(Mmat + (size_t)k * 32 + c4 * 4);
    }
    __syncthreads();

    {
        int r = tid >> 2, hf = tid & 3;    // row 0..127, col-eighth 0..3 (8 cols)
        unsigned long long a8[4];
#pragma unroll
        for (int i = 0; i < 4; i++) a8[i] = 0ull;
#pragma unroll 4
        for (int k = 0; k < 128; k++) {
            unsigned long long cd = dup2(Ct[r][k]);
            const ulonglong2* mp = (const ulonglong2*)&Ms[k][hf * 8];
            ulonglong2 m01 = mp[0], m23 = mp[1];
            unsigned long long md[4] = {m01.x, m01.y, m23.x, m23.y};
#pragma unroll
            for (int i = 0; i < 4; i++)
                asm("fma.rn.f32x2 %0, %1, %2, %0;"
                    : "+l"(a8[i]) : "l"(cd), "l"(md[i]));
        }
        float o[8];
#pragma unroll
        for (int i = 0; i < 4; i++)
            asm("mov.b64 {%0,%1}, %2;" : "=f"(o[2 * i]), "=f"(o[2 * i + 1]) : "l"(a8[i]));
        float* xp = xs + (size_t)(row0 + r) * 32 + hf * 8;
        *(float4*)(xp)     = make_float4(o[0], o[1], o[2], o[3]);
        *(float4*)(xp + 4) = make_float4(o[4], o[5], o[6], o[7]);
    }
}

// ---------------- merged precompute: q (smem) -> M, tb  (1 block) ----------
__global__ __launch_bounds__(256) void precomp_kernel(
    const float* __restrict__ vt,
    const float* __restrict__ qkvw, const float* __restrict__ qkvb,
    const float* __restrict__ aow,  const float* __restrict__ aob,
    float* __restrict__ M, float* __restrict__ tb)
{
    __shared__ float sq[NTOK * HDIM];
    int tid = threadIdx.x;
#pragma unroll
    for (int r = 0; r < 4; r++) {
        int idx = tid + r * 256;
        int t = idx >> 7, j = idx & 127;
        float acc = qkvb[j];
#pragma unroll 8
        for (int k = 0; k < 128; k++) acc += vt[t * 128 + k] * qkvw[k * 384 + j];
        sq[t * 128 + j] = acc;
    }
    __syncthreads();
#pragma unroll
    for (int r = 0; r < 16; r++) {
        int idx = tid + r * 256;
        int k = idx >> 5, col = idx & 31;
        int h = col >> 3, t = col & 7;
        float acc = 0.f;
#pragma unroll
        for (int d = 0; d < 32; d++)
            acc += qkvw[k * 384 + 128 + h * 32 + d] * sq[t * 128 + h * 32 + d];
        M[k * 32 + col] = acc * 0.17677669529663687f;
    }
    if (tid < 128) {
        int j = tid;
        float acc = aob[j];
#pragma unroll 8
        for (int d2 = 0; d2 < 128; d2++) acc += qkvb[256 + d2] * aow[d2 * 128 + j];
        tb[j] = acc;
    }
}

__global__ void wstack_kern(const float* __restrict__ qkvw,
                            const float* __restrict__ aow,
                            float* __restrict__ W2)
{
    int idx = blockIdx.x * 256 + threadIdx.x;
    int row = idx >> 7, j = idx & 127;
    int h = row >> 7, d = row & 127;
    float acc = 0.f;
#pragma unroll
    for (int d2 = 0; d2 < 32; d2++)
        acc += qkvw[d * 384 + 256 + h * 32 + d2] * aow[(h * 32 + d2) * 128 + j];
    W2[row * 128 + j] = acc;
}

// ---------------- attention + token projection, one block per graph --------
__global__ __launch_bounds__(512) void attn3_kernel(
    const float* __restrict__ xs, const float* __restrict__ X,
    const float* __restrict__ W2, const float* __restrict__ tb,
    float* __restrict__ tok)
{
    __shared__ __align__(16) float s_p[64][32];
    __shared__ __align__(16) float s_x[64][128];
    __shared__ float s_m[32], s_i[32];
    __shared__ float s_mm[16][32], s_ss[16][32];
    int b = blockIdx.x, tid = threadIdx.x;

    {
        int c = tid & 31, r16 = tid >> 5;
        float m = -1e30f, ssum = 0.f;
        const float* p = xs + (size_t)b * NPG * 32 + r16 * 32 + c;
        for (int n = r16; n < NPG; n += 16, p += 512) {
            float v = *p;
            if (v > m) { ssum = ssum * __expf(m - v) + 1.f; m = v; }
            else ssum += __expf(v - m);
        }
        s_mm[r16][c] = m; s_ss[r16][c] = ssum;
    }
    __syncthreads();
    if (tid < 32) {
        float M = -1e30f, S = 0.f;
#pragma unroll
        for (int r = 0; r < 16; r++) {
            float m = s_mm[r][tid], s = s_ss[r][tid];
            if (m > M) { S = S * __expf(M - m) + s; M = m; }
            else S += s * __expf(m - M);
        }
        s_m[tid] = M; s_i[tid] = 1.f / S;
    }
    __syncthreads();

    int d = tid & 127, q = tid >> 7;
    unsigned long long acc2[16];
#pragma unroll
    for (int i = 0; i < 16; i++) acc2[i] = 0ull;

    for (int cb = 0; cb < 16; cb++) {
        if (cb) __syncthreads();
        for (int q2 = tid; q2 < 2048; q2 += 512) {
            int r = q2 >> 5, c4 = q2 & 31;
            *(float4*)&s_x[r][c4 * 4] =
                *(const float4*)(X + ((size_t)b * NPG + cb * 64 + r) * HDIM + c4 * 4);
        }
        for (int q2 = tid; q2 < 2048; q2 += 512) {
            int r = q2 >> 5, c = q2 & 31;
            float v = xs[((size_t)b * NPG + cb * 64 + r) * 32 + c];
            s_p[r][c] = __expf(v - s_m[c]) * s_i[c];
        }
        __syncthreads();
        int n0 = q * 16;
#pragma unroll 4
        for (int n = 0; n < 16; n++) {
            const ulonglong2* pr = (const ulonglong2*)&s_p[n0 + n][0];
            ulonglong2 u0 = pr[0], u1 = pr[1], u2 = pr[2], u3 = pr[3];
            ulonglong2 u4 = pr[4], u5 = pr[5], u6 = pr[6], u7 = pr[7];
            unsigned long long pd[16] = {u0.x, u0.y, u1.x, u1.y,
                                         u2.x, u2.y, u3.x, u3.y,
                                         u4.x, u4.y, u5.x, u5.y,
                                         u6.x, u6.y, u7.x, u7.y};
            unsigned long long xv = dup2(s_x[n0 + n][d]);
#pragma unroll
            for (int i = 0; i < 16; i++)
                asm("fma.rn.f32x2 %0, %1, %2, %0;"
                    : "+l"(acc2[i]) : "l"(xv), "l"(pd[i]));
        }
    }
    __syncthreads();
    float* P0 = &s_x[0][0];
    float* P1 = &s_x[32][0];
    if (q >= 2) {
        float* P = (q == 2) ? P0 : P1;
#pragma unroll
        for (int i = 0; i < 16; i++) {
            float f0, f1;
            asm("mov.b64 {%0,%1}, %2;" : "=f"(f0), "=f"(f1) : "l"(acc2[i]));
            P[(2 * i) * 128 + d]     = f0;
            P[(2 * i + 1) * 128 + d] = f1;
        }
    }
    __syncthreads();
    if (q < 2) {
        float* P = (q == 0) ? P0 : P1;
#pragma unroll
        for (int i = 0; i < 16; i++) {
            float f0, f1;
            asm("mov.b64 {%0,%1}, %2;" : "=f"(f0), "=f"(f1) : "l"(acc2[i]));
            P[(2 * i) * 128 + d]     += f0;
            P[(2 * i + 1) * 128 + d] += f1;
        }
    }
    __syncthreads();
    if (q < 2) {
#pragma unroll
        for (int c = 0; c < 16; c++) {
            int cc = q * 16 + c;
            P0[cc * 128 + d] += P1[cc * 128 + d];
        }
    }
    __syncthreads();

    {
        int j = tid & 127, tg = tid >> 7;
        float o0 = tb[j], o1 = o0;
        for (int k = 0; k < 512; k += 4) {
            float wv0 = W2[(k + 0) * 128 + j];
            float wv1 = W2[(k + 1) * 128 + j];
            float wv2 = W2[(k + 2) * 128 + j];
            float wv3 = W2[(k + 3) * 128 + j];
            int h = k >> 7, dk = k & 127;
            const float* y0 = &P0[((h << 3) + tg * 2) * 128 + dk];
            const float* y1 = &P0[((h << 3) + tg * 2 + 1) * 128 + dk];
            float4 v0 = *(const float4*)y0;
            float4 v1 = *(const float4*)y1;
            o0 += v0.x * wv0 + v0.y * wv1 + v0.z * wv2 + v0.w * wv3;
            o1 += v1.x * wv0 + v1.y * wv1 + v1.z * wv2 + v1.w * wv3;
        }
        tok[((size_t)b * NTOK + tg * 2) * HDIM + j]     = o0;
        tok[((size_t)b * NTOK + tg * 2 + 1) * HDIM + j] = o1;
    }
}

// ---------------- whole Mamba block per sequence (128 blocks) --------------
__device__ __forceinline__ float siluf(float v) { return v / (1.0f + expf(-v)); }

__global__ __launch_bounds__(256) void mamba_kernel(
    const float* __restrict__ tok,
    const float* __restrict__ in_w,  const float* __restrict__ conv_w,
    const float* __restrict__ conv_b,const float* __restrict__ x_w,
    const float* __restrict__ dt_w,  const float* __restrict__ dt_b,
    const float* __restrict__ A_log, const float* __restrict__ Dp,
    const float* __restrict__ out_w, const float* __restrict__ norm_w,
    const float* __restrict__ normf_w, float* __restrict__ gf)
{
    __shared__ float s_res[NTOK][HDIM];
    __shared__ float s_h  [NTOK][HDIM];
    __shared__ float s_u  [NTOK][MI];
    __shared__ float s_gt [NTOK][MI];
    __shared__ float s_dt [NTOK][MI];
    __shared__ float s_ssm[NTOK][MR + 2 * MS];
    __shared__ float s_y  [NTOK][MI];
    int b = blockIdx.x, tid = threadIdx.x;

    for (int idx = tid; idx < NTOK * HDIM; idx += 256)
        s_res[idx >> 7][idx & 127] = tok[b * NTOK * HDIM + idx];
    __syncthreads();
    {
        int t = tid >> 5, lane = tid & 31;
        float ss = 0.f;
        for (int j = lane; j < HDIM; j += 32) { float v = s_res[t][j]; ss += v * v; }
#pragma unroll
        for (int o = 16; o > 0; o >>= 1) ss += __shfl_xor_sync(~0u, ss, o);
        float rs = rsqrtf(ss * (1.0f / HDIM) + 1e-5f);
        for (int j = lane; j < HDIM; j += 32) s_h[t][j] = s_res[t][j] * rs * norm_w[j];
    }
    __syncthreads();
    {
        float accA[NTOK], accB[NTOK];
#pragma unroll
        for (int t = 0; t < NTOK; t++) { accA[t] = 0.f; accB[t] = 0.f; }
        const float* wp = in_w + tid;
#pragma unroll 4
        for (int k = 0; k < HDIM; k++) {
            float w0 = wp[k * 512];
            float w1 = wp[k * 512 + 256];
#pragma unroll
            for (int t = 0; t < NTOK; t++) {
                float h = s_h[t][k];
                accA[t] += h * w0;
                accB[t] += h * w1;
            }
        }
#pragma unroll
        for (int t = 0; t < NTOK; t++) {
            s_u[t][tid] = accA[t];
            s_gt[t][tid] = accB[t];
        }
    }
    __syncthreads();
    {
        int i = tid;
        float cw[MK];
#pragma unroll
        for (int k = 0; k < MK; k++) cw[k] = conv_w[i * MK + k];
        float cb = conv_b[i];
        float uv[NTOK];
#pragma unroll
        for (int t = 0; t < NTOK; t++) uv[t] = s_u[t][i];
#pragma unroll
        for (int t = NTOK - 1; t >= 0; t--) {
            float v = cb;
#pragma unroll
            for (int k = 0; k < MK; k++) {
                int tt = t + k - (MK - 1);
                if (tt >= 0) v += cw[k] * uv[tt];
            }
            uv[t] = siluf(v);
        }
#pragma unroll
        for (int t = 0; t < NTOK; t++) s_u[t][i] = uv[t];
    }
    __syncthreads();
    for (int idx = tid; idx < NTOK * (MR + 2 * MS); idx += 256) {
        int t = idx / 40, c = idx % 40;
        float acc = 0.f;
#pragma unroll 8
        for (int i = 0; i < MI; i++) acc += s_u[t][i] * x_w[i * 40 + c];
        s_ssm[t][c] = acc;
    }
    __syncthreads();
    for (int idx = tid; idx < NTOK * MI; idx += 256) {
        int t = idx >> 8, i = idx & 255;
        float acc = dt_b[i];
#pragma unroll
        for (int r = 0; r < MR; r++) acc += s_ssm[t][r] * dt_w[r * MI + i];
        s_dt[t][i] = fmaxf(acc, 0.f) + log1pf(expf(-fabsf(acc)));
    }
    __syncthreads();
    {
        int i = tid;
        float st[MS], Ar[MS];
#pragma unroll
        for (int s = 0; s < MS; s++) { st[s] = 0.f; Ar[s] = -expf(A_log[i * MS + s]); }
        float Dv = Dp[i];
#pragma unroll
        for (int t = 0; t < NTOK; t++) {
            float dtv = s_dt[t][i], uv = s_u[t][i];
            float y = 0.f;
#pragma unroll
            for (int s = 0; s < MS; s++) {
                float dA = expf(dtv * Ar[s]);
                st[s] = dA * st[s] + dtv * s_ssm[t][MR + s] * uv;
                y += st[s] * s_ssm[t][MR + MS + s];
            }
            y += uv * Dv;
            y *= siluf(s_gt[t][i]);
            s_y[t][i] = y;
        }
    }
    __syncthreads();
    {
        int j = tid & 127, t2 = tid >> 7;
        float acc[4] = {0.f, 0.f, 0.f, 0.f};
        const float* wp = out_w + j;
#pragma unroll 8
        for (int i = 0; i < MI; i++) {
            float w = wp[i * 128];
#pragma unroll
            for (int q = 0; q < 4; q++) acc[q] += s_y[t2 + 2 * q][i] * w;
        }
#pragma unroll
        for (int q = 0; q < 4; q++) {
            int t = t2 + 2 * q;
            s_h[t][j] = s_res[t][j] + acc[q];
        }
    }
    __syncthreads();
    {
        int t = tid >> 5, lane = tid & 31;
        float ss = 0.f;
        for (int j = lane; j < HDIM; j += 32) { float v = s_h[t][j]; ss += v * v; }
#pragma unroll
        for (int o = 16; o > 0; o >>= 1) ss += __shfl_xor_sync(~0u, ss, o);
        float rs = rsqrtf(ss * (1.0f / HDIM) + 1e-5f);
        for (int j = lane; j < HDIM; j += 32) s_h[t][j] = s_h[t][j] * rs * normf_w[j];
    }
    __syncthreads();
    for (int j = tid; j < HDIM; j += 256) {
        float acc = 0.f;
#pragma unroll
        for (int t = 0; t < NTOK; t++) acc += s_h[t][j];
        gf[b * HDIM + j] = acc * 0.125f;
    }
}

// ---------------- host driver ----------------------------------------------
extern "C" void kernel_launch(void* const* d_in, const int* in_sizes, int n_in,
                              void* d_out, int out_size)
{
    const float* x_in    = (const float*)d_in[0];
    const int*   ei      = (const int*)  d_in[1];
    const float* w_in    = (const float*)d_in[5];
    const float* b_in    = (const float*)d_in[6];
    const float* gin_w   = (const float*)d_in[7];
    const float* gin_b   = (const float*)d_in[8];
    const float* vt      = (const float*)d_in[9];
    const float* qkv_w   = (const float*)d_in[10];
    const float* qkv_b   = (const float*)d_in[11];
    const float* ao_w    = (const float*)d_in[12];
    const float* ao_b    = (const float*)d_in[13];
    const float* m_in_w  = (const float*)d_in[14];
    const float* m_conv_w= (const float*)d_in[15];
    const float* m_conv_b= (const float*)d_in[16];
    const float* m_x_w   = (const float*)d_in[17];
    const float* m_dt_w  = (const float*)d_in[18];
    const float* m_dt_b  = (const float*)d_in[19];
    const float* m_A_log = (const float*)d_in[20];
    const float* m_D     = (const float*)d_in[21];
    const float* m_out_w = (const float*)d_in[22];
    const float* m_norm_w  = (const float*)d_in[23];
    const float* m_normf_w = (const float*)d_in[24];
    const float* w_out   = (const float*)d_in[25];
    const float* b_out   = (const float*)d_in[26];

    const int N = in_sizes[0] / HDIM;
    const int E = in_sizes[1] / 2;

    float *xa, *xcur, *xs, *Mb, *W2, *tb, *tk, *gf, *S;
    int *deg, *off, *cur, *bsum, *ssrc;
    cudaGetSymbolAddress((void**)&xa,   g_xa);
    cudaGetSymbolAddress((void**)&xcur, g_xcur);
    cudaGetSymbolAddress((void**)&xs,   g_xs);
    cudaGetSymbolAddress((void**)&Mb,   g_M);
    cudaGetSymbolAddress((void**)&W2,   g_W2);
    cudaGetSymbolAddress((void**)&tb,   g_tb);
    cudaGetSymbolAddress((void**)&tk,   g_tok);
    cudaGetSymbolAddress((void**)&gf,   g_gf);
    cudaGetSymbolAddress((void**)&S,    g_S);
    cudaGetSymbolAddress((void**)&deg,  g_deg);
    cudaGetSymbolAddress((void**)&off,  g_off);
    cudaGetSymbolAddress((void**)&cur,  g_cur);
    cudaGetSymbolAddress((void**)&bsum, g_bsum);
    cudaGetSymbolAddress((void**)&ssrc, g_ssrc);

    cudaFuncSetAttribute(gemm_t,
                         cudaFuncAttributeMaxDynamicSharedMemorySize, GEMM_SMEM);

    cudaStream_t s2;
    cudaStreamCreateWithFlags(&s2, cudaStreamNonBlocking);
    cudaEvent_t evF, evJ, eA, eB;
    cudaEventCreateWithFlags(&evF, cudaEventDisableTiming);
    cudaEventCreateWithFlags(&evJ, cudaEventDisableTiming);
    cudaEventCreateWithFlags(&eA, cudaEventDisableTiming);
    cudaEventCreateWithFlags(&eB, cudaEventDisableTiming);

    // ---- CSR build (parallel scan); S memset hoisted ----
    cudaMemsetAsync(S, 0, NGRAPH * HDIM * sizeof(float));
    cudaMemsetAsync(deg, 0, (size_t)N * sizeof(int));

    // fork s2 from the capturing stream BEFORE any work lands on it
    cudaEventRecord(evF, 0);
    cudaStreamWaitEvent(s2, evF, 0);

    const int E2 = E / 2;
    hist_kernel<<<(E2 + 255) / 256, 256>>>((const int2*)(ei + E), E2, deg);
    blocksum_kernel<<<512, 256>>>(deg, bsum);
    scanb_kernel<<<1, 512>>>(bsum);
    offsets_kernel<<<512, 256>>>(deg, bsum, off, cur);
    scatter_kernel<<<(E2 + 255) / 256, 256>>>((const int2*)ei, (const int2*)(ei + E),
                                              E2, cur, ssrc);

    // ---- per-layer weight precompute (both layers) on forked side stream --
    for (int l = 0; l < 2; l++) {
        const float* qkvw_l = qkv_w + (size_t)l * 128 * 384;
        const float* qkvb_l = qkv_b + l * 384;
        const float* aow_l  = ao_w + (size_t)l * 128 * 128;
        wstack_kern<<<256, 256, 0, s2>>>(qkvw_l, aow_l, W2 + (size_t)l * 4 * HDIM * HDIM);
        precomp_kernel<<<1, 256, 0, s2>>>(vt + (size_t)l * NTOK * 128,
                                          qkvw_l, qkvb_l, aow_l, ao_b + l * 128,
                                          Mb + (size_t)l * HDIM * 32, tb + l * HDIM);
    }
    cudaEventRecord(evJ, s2);
    cudaStreamWaitEvent(0, evJ, 0);

    const int aggBlocks = N / 8;
    const int halfAgg = N / 16;
    const int halfGemm = N / 256;

    // x = gin(x_in) — 2-chunk pipelined gather/gemm (gather reads x_in only)
    cudaEventRecord(evF, 0);
    cudaStreamWaitEvent(s2, evF, 0);
    csr_agg_kernel<<<halfAgg, 256, 0, s2>>>(x_in, 0, off, ssrc, xa);
    cudaEventRecord(eA, s2);
    csr_agg_kernel<<<halfAgg, 256, 0, s2>>>(x_in, N / 2, off, ssrc, xa);
    cudaEventRecord(eB, s2);
    cudaStreamWaitEvent(0, eA, 0);
    gemm_t<<<halfGemm, 512, GEMM_SMEM>>>(xa, 0, w_in, 128, b_in, 1.f, nullptr,
                                         xcur, Mb, xs);
    cudaStreamWaitEvent(0, eB, 0);
    gemm_t<<<halfGemm, 512, GEMM_SMEM>>>(xa, N / 2, w_in, 128, b_in, 1.f, nullptr,
                                         xcur, Mb, xs);

    for (int l = 0; l < 2; l++) {
        // fork: csr_agg(xcur) on side stream
        cudaEventRecord(evF, 0);
        cudaStreamWaitEvent(s2, evF, 0);
        csr_agg_kernel<<<aggBlocks, 256, 0, s2>>>(xcur, 0, off, ssrc, xa);
        cudaEventRecord(evJ, s2);

        // main stream: attention + mamba (read xcur/xs)
        attn3_kernel<<<NGRAPH, 512>>>(xs, xcur, W2 + (size_t)l * 4 * HDIM * HDIM,
                                      tb + l * HDIM, tk);
        mamba_kernel<<<NGRAPH, 256>>>(tk, m_in_w, m_conv_w, m_conv_b, m_x_w,
                                      m_dt_w, m_dt_b, m_A_log, m_D, m_out_w,
                                      m_norm_w, m_normf_w, gf);

        // join, GIN GEMM (+ fused xs for next layer if any)
        cudaStreamWaitEvent(0, evJ, 0);
        const float* Mn = (l == 0) ? Mb + (size_t)HDIM * 32 : nullptr;
        float* xsn = (l == 0) ? xs : nullptr;
        gemm_t<<<N / 128, 512, GEMM_SMEM>>>(xa, 0, gin_w + (size_t)l * 128 * 128, 128,
                                            gin_b + l * 128, 1.f, gf, xcur,
                                            Mn, xsn);
    }

    // final: out = (sum_g (x+agg)) @ w_out + 1024*b_out
    csr_sum_kernel<<<N / 8, 256>>>(xcur, off, ssrc, S);
    gemm_t<<<1, 512, GEMM_SMEM>>>(S, 0, w_out, 128, b_out, 1024.f, nullptr,
                                  (float*)d_out, nullptr, nullptr);

    cudaEventDestroy(evF);
    cudaEventDestroy(evJ);
    cudaEventDestroy(eA);
    cudaEventDestroy(eB);
    cudaStreamDestroy(s2);
}

// round 17
// speedup vs baseline: 1.0022x; 1.0022x over previous
#include <cuda_runtime.h>
#include <cstdint>
#include <math.h>

// ---------------- problem constants (fixed by setup_inputs) ----------------
#define NNODES 131072
#define NEDGE  2097152
#define HDIM   128
#define NGRAPH 128
#define NPG    1024
#define NTOK   8
#define NHEAD  4
#define HD     32
#define MI     256   // mamba intermediate
#define MS     16    // mamba state
#define MR     8     // dt rank
#define MK     4     // conv kernel

// ---------------- device scratch (no allocation allowed) -------------------
__device__ __align__(16) float g_xa  [NNODES*HDIM];
__device__ __align__(16) float g_xcur[NNODES*HDIM];
__device__ __align__(16) float g_xs  [NNODES*32];
__device__ __align__(16) float g_M   [2*HDIM*32];
__device__ __align__(16) float g_W2  [2*4*HDIM*HDIM];
__device__ __align__(16) float g_tb  [2*HDIM];
__device__ __align__(16) float g_tok [NGRAPH*NTOK*HDIM];
__device__ __align__(16) float g_gf  [NGRAPH*HDIM];
__device__ __align__(16) float g_S   [NGRAPH*HDIM];
__device__ int g_deg [NNODES];
__device__ int g_off [NNODES + 1];
__device__ int g_cur [NNODES];
__device__ int g_bsum[512];
__device__ int g_ssrc[NEDGE];

__device__ __forceinline__ unsigned long long dup2(float v) {
    unsigned long long r;
    asm("mov.b64 %0,{%1,%1};" : "=l"(r) : "f"(v));
    return r;
}

// ---------------- CSR build: histogram -> 3-phase scan -> scatter ----------
__global__ __launch_bounds__(256) void hist_kernel(
    const int2* __restrict__ eid, int E2, int* __restrict__ deg)
{
    int e = blockIdx.x * 256 + threadIdx.x;
    if (e < E2) {
        int2 d = eid[e];
        atomicAdd(&deg[d.x], 1);
        atomicAdd(&deg[d.y], 1);
    }
}

__global__ __launch_bounds__(256) void blocksum_kernel(
    const int* __restrict__ deg, int* __restrict__ bsum)
{
    __shared__ int sh[256];
    int t = threadIdx.x;
    sh[t] = deg[blockIdx.x * 256 + t];
    __syncthreads();
#pragma unroll
    for (int o = 128; o > 0; o >>= 1) {
        if (t < o) sh[t] += sh[t + o];
        __syncthreads();
    }
    if (t == 0) bsum[blockIdx.x] = sh[0];
}

__global__ __launch_bounds__(512) void scanb_kernel(int* __restrict__ bsum)
{
    __shared__ int sh[512];
    int t = threadIdx.x;
    int v = bsum[t];
    sh[t] = v;
    __syncthreads();
    for (int o = 1; o < 512; o <<= 1) {
        int u = (t >= o) ? sh[t - o] : 0;
        __syncthreads();
        sh[t] += u;
        __syncthreads();
    }
    bsum[t] = sh[t] - v;
}

__global__ __launch_bounds__(256) void offsets_kernel(
    const int* __restrict__ deg, const int* __restrict__ bsum,
    int* __restrict__ off, int* __restrict__ cur)
{
    __shared__ int sh[256];
    int t = threadIdx.x;
    int base = blockIdx.x * 256;
    int d = deg[base + t];
    sh[t] = d;
    __syncthreads();
    for (int o = 1; o < 256; o <<= 1) {
        int u = (t >= o) ? sh[t - o] : 0;
        __syncthreads();
        sh[t] += u;
        __syncthreads();
    }
    int o_excl = bsum[blockIdx.x] + sh[t] - d;
    off[base + t] = o_excl;
    cur[base + t] = o_excl;
    if (blockIdx.x == 511 && t == 255) off[NNODES] = bsum[511] + sh[255];
}

__global__ __launch_bounds__(256) void scatter_kernel(
    const int2* __restrict__ eis, const int2* __restrict__ eid, int E2,
    int* __restrict__ cur, int* __restrict__ ssrc)
{
    int e = blockIdx.x * 256 + threadIdx.x;
    if (e >= E2) return;
    int2 s = eis[e];
    int2 d = eid[e];
    ssrc[atomicAdd(&cur[d.x], 1)] = s.x;
    ssrc[atomicAdd(&cur[d.y], 1)] = s.y;
}

// ---------------- gather helper: acc = x[nd] + sum_{src} x[src] ------------
__device__ __forceinline__ float4 gather_row(
    const float* __restrict__ x, const int* __restrict__ off,
    const int* __restrict__ ssrc, int nd, int lane)
{
    int s = off[nd], e = off[nd + 1];
    float4 acc = *(const float4*)(x + (size_t)nd * HDIM + lane * 4);
    int i = s;
    int n8 = s + ((e - s) & ~7);
    for (; i < n8; i += 8) {
        int id[8];
#pragma unroll
        for (int j = 0; j < 8; j++) id[j] = __ldg(&ssrc[i + j]);
        float4 v[8];
#pragma unroll
        for (int j = 0; j < 8; j++)
            v[j] = *(const float4*)(x + (size_t)id[j] * HDIM + lane * 4);
#pragma unroll
        for (int j = 0; j < 8; j++) {
            acc.x += v[j].x; acc.y += v[j].y; acc.z += v[j].z; acc.w += v[j].w;
        }
    }
    for (; i < e; i++) {
        int s0 = __ldg(&ssrc[i]);
        float4 v = *(const float4*)(x + (size_t)s0 * HDIM + lane * 4);
        acc.x += v.x; acc.y += v.y; acc.z += v.z; acc.w += v.w;
    }
    return acc;
}

__global__ __launch_bounds__(256) void csr_agg_kernel(
    const float* __restrict__ x, const int* __restrict__ off,
    const int* __restrict__ ssrc, float* __restrict__ xa)
{
    int nd = blockIdx.x * 8 + (threadIdx.x >> 5);
    int lane = threadIdx.x & 31;
    float4 acc = gather_row(x, off, ssrc, nd, lane);
    *(float4*)(xa + (size_t)nd * HDIM + lane * 4) = acc;
}

__global__ __launch_bounds__(256) void csr_sum_kernel(
    const float* __restrict__ x, const int* __restrict__ off,
    const int* __restrict__ ssrc, float* __restrict__ S)
{
    __shared__ float sh[8][HDIM];
    int w = threadIdx.x >> 5, lane = threadIdx.x & 31;
    int nd = blockIdx.x * 8 + w;
    float4 acc = gather_row(x, off, ssrc, nd, lane);
    *(float4*)&sh[w][lane * 4] = acc;
    __syncthreads();
    if (threadIdx.x < 32) {
        float4 t = make_float4(0.f, 0.f, 0.f, 0.f);
#pragma unroll
        for (int r = 0; r < 8; r++) {
            float4 v = *(const float4*)&sh[r][threadIdx.x * 4];
            t.x += v.x; t.y += v.y; t.z += v.z; t.w += v.w;
        }
        int g = (blockIdx.x * 8) >> 10;
        float* ap = S + g * HDIM + threadIdx.x * 4;
        asm volatile("red.global.add.v4.f32 [%0], {%1,%2,%3,%4};"
                     :: "l"(ap), "f"(t.x), "f"(t.y), "f"(t.z), "f"(t.w) : "memory");
    }
}

// ---------------- GEMM: C = A @ W + bs*bias [+ gf] [+ fused xs = C @ M] ----
// R15 layout, but launch_bounds(256,1): lift the 128-reg cap so the 64-reg
// FFMA2 accumulator bank stays register-resident (spill-hypothesis test).
#define GEMM_SMEM (128*132*4 + 2*32*132*4)
__global__ __launch_bounds__(256, 1) void gemm_t(
    const float* __restrict__ A,
    const float* __restrict__ W, int ldw,
    const float* __restrict__ bias, float bias_scale,
    const float* __restrict__ gf,
    float* __restrict__ C,
    const float* __restrict__ Mmat, float* __restrict__ xs)
{
    extern __shared__ char gsm[];
    float (*Wf)[132]     = (float(*)[132])gsm;                       // [k][col]
    float (*As)[32][132] = (float(*)[32][132])(gsm + 128 * 132 * 4); // [buf][k][row]
    int tid = threadIdx.x;
    int row0 = blockIdx.x * 128;
    int tx = tid & 15, ty = tid >> 4;

#pragma unroll
    for (int it = 0; it < 16; it++) {
        int lin = tid + it * 256;
        int k = lin >> 5, c4 = lin & 31;
        *(float4*)&Wf[k][c4 * 4] = *(const float4*)(W + (size_t)k * ldw + c4 * 4);
    }

    float4 areg[4];
#pragma unroll
    for (int it = 0; it < 4; it++) {
        int lin = tid + it * 256;
        int row = lin >> 3, c4 = lin & 7;
        areg[it] = *(const float4*)(A + (size_t)(row0 + row) * HDIM + c4 * 4);
    }
#pragma unroll
    for (int it = 0; it < 4; it++) {
        int lin = tid + it * 256;
        int row = lin >> 3, c4 = lin & 7;
        As[0][c4 * 4 + 0][row] = areg[it].x;
        As[0][c4 * 4 + 1][row] = areg[it].y;
        As[0][c4 * 4 + 2][row] = areg[it].z;
        As[0][c4 * 4 + 3][row] = areg[it].w;
    }
    __syncthreads();

    unsigned long long acc[4][8];
#pragma unroll
    for (int i = 0; i < 4; i++)
#pragma unroll
        for (int j = 0; j < 8; j++) acc[i][j] = 0ull;

#pragma unroll
    for (int c = 0; c < 4; c++) {
        if (c < 3) {
#pragma unroll
            for (int it = 0; it < 4; it++) {
                int lin = tid + it * 256;
                int row = lin >> 3, c4 = lin & 7;
                areg[it] = *(const float4*)(A + (size_t)(row0 + row) * HDIM
                                            + (c + 1) * 32 + c4 * 4);
            }
        }
        int buf = c & 1;
#pragma unroll
        for (int kk = 0; kk < 32; kk++) {
            int kg = c * 32 + kk;
            ulonglong2 a01 = *(const ulonglong2*)&As[buf][kk][ty * 8];
            ulonglong2 a23 = *(const ulonglong2*)&As[buf][kk][ty * 8 + 4];
            float4 w0 = *(const float4*)&Wf[kg][tx * 8];
            float4 w1 = *(const float4*)&Wf[kg][tx * 8 + 4];
            unsigned long long ap[4] = {a01.x, a01.y, a23.x, a23.y};
            unsigned long long wd[8] = {dup2(w0.x), dup2(w0.y), dup2(w0.z), dup2(w0.w),
                                        dup2(w1.x), dup2(w1.y), dup2(w1.z), dup2(w1.w)};
#pragma unroll
            for (int i = 0; i < 4; i++)
#pragma unroll
                for (int j = 0; j < 8; j++)
                    asm("fma.rn.f32x2 %0, %1, %2, %0;"
                        : "+l"(acc[i][j]) : "l"(ap[i]), "l"(wd[j]));
        }
        if (c < 3) {
            __syncthreads();
            int nbuf = (c + 1) & 1;
#pragma unroll
            for (int it = 0; it < 4; it++) {
                int lin = tid + it * 256;
                int row = lin >> 3, c4 = lin & 7;
                As[nbuf][c4 * 4 + 0][row] = areg[it].x;
                As[nbuf][c4 * 4 + 1][row] = areg[it].y;
                As[nbuf][c4 * 4 + 2][row] = areg[it].z;
                As[nbuf][c4 * 4 + 3][row] = areg[it].w;
            }
            __syncthreads();
        }
    }

    int jc0 = tx * 8;
    float bj[8];
#pragma unroll
    for (int j = 0; j < 8; j++)
        bj[j] = bias ? bias_scale * bias[jc0 + j] : 0.f;
    if (gf) {
        int grp = row0 >> 10;
#pragma unroll
        for (int j = 0; j < 8; j++) bj[j] += gf[grp * HDIM + jc0 + j];
    }
#pragma unroll
    for (int i = 0; i < 4; i++) {
        int rlo = row0 + ty * 8 + 2 * i;
        float lo[8], hi[8];
#pragma unroll
        for (int j = 0; j < 8; j++)
            asm("mov.b64 {%0,%1}, %2;" : "=f"(lo[j]), "=f"(hi[j]) : "l"(acc[i][j]));
        *(float4*)(C + (size_t)rlo * HDIM + jc0) =
            make_float4(lo[0] + bj[0], lo[1] + bj[1], lo[2] + bj[2], lo[3] + bj[3]);
        *(float4*)(C + (size_t)rlo * HDIM + jc0 + 4) =
            make_float4(lo[4] + bj[4], lo[5] + bj[5], lo[6] + bj[6], lo[7] + bj[7]);
        *(float4*)(C + (size_t)(rlo + 1) * HDIM + jc0) =
            make_float4(hi[0] + bj[0], hi[1] + bj[1], hi[2] + bj[2], hi[3] + bj[3]);
        *(float4*)(C + (size_t)(rlo + 1) * HDIM + jc0 + 4) =
            make_float4(hi[4] + bj[4], hi[5] + bj[5], hi[6] + bj[6], hi[7] + bj[7]);
    }

    if (!xs) return;

    // ---- fused scores epilogue: xs(block rows) = C_tile @ M ----
    __syncthreads();
    float (*Ct)[132] = Wf;
    float (*Ms)[32]  = (float(*)[32])&As[0][0][0];
#pragma unroll
    for (int i = 0; i < 4; i++) {
        int rl = ty * 8 + 2 * i;
        float lo[8], hi[8];
#pragma unroll
        for (int j = 0; j < 8; j++)
            asm("mov.b64 {%0,%1}, %2;" : "=f"(lo[j]), "=f"(hi[j]) : "l"(acc[i][j]));
#pragma unroll
        for (int j = 0; j < 8; j++) {
            Ct[rl][jc0 + j]     = lo[j] + bj[j];
            Ct[rl + 1][jc0 + j] = hi[j] + bj[j];
        }
    }
#pragma unroll
    for (int it = 0; it < 4; it++) {
        int lin = tid + it * 256;
        int k = lin >> 3, c4 = lin & 7;
        *(float4*)&Ms[k][c4 * 4] = *(const float4*)(Mmat + (size_t)k * 32 + c4 * 4);
    }
    __syncthreads();

    {
        int r = tid >> 1, hf = tid & 1;
        unsigned long long a16[8];
#pragma unroll
        for (int i = 0; i < 8; i++) a16[i] = 0ull;
#pragma unroll 4
        for (int k = 0; k < 128; k++) {
            unsigned long long cd = dup2(Ct[r][k]);
            const ulonglong2* mp = (const ulonglong2*)&Ms[k][hf * 16];
            ulonglong2 m01 = mp[0], m23 = mp[1], m45 = mp[2], m67 = mp[3];
            unsigned long long md[8] = {m01.x, m01.y, m23.x, m23.y,
                                        m45.x, m45.y, m67.x, m67.y};
#pragma unroll
            for (int i = 0; i < 8; i++)
                asm("fma.rn.f32x2 %0, %1, %2, %0;"
                    : "+l"(a16[i]) : "l"(cd), "l"(md[i]));
        }
        float o[16];
#pragma unroll
        for (int i = 0; i < 8; i++)
            asm("mov.b64 {%0,%1}, %2;" : "=f"(o[2 * i]), "=f"(o[2 * i + 1]) : "l"(a16[i]));
        float* xp = xs + (size_t)(row0 + r) * 32 + hf * 16;
#pragma unroll
        for (int i = 0; i < 4; i++)
            *(float4*)(xp + i * 4) = make_float4(o[4 * i], o[4 * i + 1],
                                                 o[4 * i + 2], o[4 * i + 3]);
    }
}

// ---------------- merged precompute: q (smem) -> M, tb  (1 block) ----------
__global__ __launch_bounds__(256) void precomp_kernel(
    const float* __restrict__ vt,
    const float* __restrict__ qkvw, const float* __restrict__ qkvb,
    const float* __restrict__ aow,  const float* __restrict__ aob,
    float* __restrict__ M, float* __restrict__ tb)
{
    __shared__ float sq[NTOK * HDIM];
    int tid = threadIdx.x;
#pragma unroll
    for (int r = 0; r < 4; r++) {
        int idx = tid + r * 256;
        int t = idx >> 7, j = idx & 127;
        float acc = qkvb[j];
#pragma unroll 8
        for (int k = 0; k < 128; k++) acc += vt[t * 128 + k] * qkvw[k * 384 + j];
        sq[t * 128 + j] = acc;
    }
    __syncthreads();
#pragma unroll
    for (int r = 0; r < 16; r++) {
        int idx = tid + r * 256;
        int k = idx >> 5, col = idx & 31;
        int h = col >> 3, t = col & 7;
        float acc = 0.f;
#pragma unroll
        for (int d = 0; d < 32; d++)
            acc += qkvw[k * 384 + 128 + h * 32 + d] * sq[t * 128 + h * 32 + d];
        M[k * 32 + col] = acc * 0.17677669529663687f;
    }
    if (tid < 128) {
        int j = tid;
        float acc = aob[j];
#pragma unroll 8
        for (int d2 = 0; d2 < 128; d2++) acc += qkvb[256 + d2] * aow[d2 * 128 + j];
        tb[j] = acc;
    }
}

__global__ void wstack_kern(const float* __restrict__ qkvw,
                            const float* __restrict__ aow,
                            float* __restrict__ W2)
{
    int idx = blockIdx.x * 256 + threadIdx.x;
    int row = idx >> 7, j = idx & 127;
    int h = row >> 7, d = row & 127;
    float acc = 0.f;
#pragma unroll
    for (int d2 = 0; d2 < 32; d2++)
        acc += qkvw[d * 384 + 256 + h * 32 + d2] * aow[(h * 32 + d2) * 128 + j];
    W2[row * 128 + j] = acc;
}

// ---------------- attention + token projection, one block per graph --------
// 512 threads: 4 quarters over the n-dimension for 2x warp parallelism.
__global__ __launch_bounds__(512) void attn3_kernel(
    const float* __restrict__ xs, const float* __restrict__ X,
    const float* __restrict__ W2, const float* __restrict__ tb,
    float* __restrict__ tok)
{
    __shared__ __align__(16) float s_p[64][32];
    __shared__ __align__(16) float s_x[64][128];
    __shared__ float s_m[32], s_i[32];
    __shared__ float s_mm[16][32], s_ss[16][32];
    int b = blockIdx.x, tid = threadIdx.x;

    {
        int c = tid & 31, r16 = tid >> 5;
        float m = -1e30f, ssum = 0.f;
        const float* p = xs + (size_t)b * NPG * 32 + r16 * 32 + c;
        for (int n = r16; n < NPG; n += 16, p += 512) {
            float v = *p;
            if (v > m) { ssum = ssum * __expf(m - v) + 1.f; m = v; }
            else ssum += __expf(v - m);
        }
        s_mm[r16][c] = m; s_ss[r16][c] = ssum;
    }
    __syncthreads();
    if (tid < 32) {
        float M = -1e30f, S = 0.f;
#pragma unroll
        for (int r = 0; r < 16; r++) {
            float m = s_mm[r][tid], s = s_ss[r][tid];
            if (m > M) { S = S * __expf(M - m) + s; M = m; }
            else S += s * __expf(m - M);
        }
        s_m[tid] = M; s_i[tid] = 1.f / S;
    }
    __syncthreads();

    int d = tid & 127, q = tid >> 7;
    unsigned long long acc2[16];
#pragma unroll
    for (int i = 0; i < 16; i++) acc2[i] = 0ull;

    for (int cb = 0; cb < 16; cb++) {
        if (cb) __syncthreads();
        for (int q2 = tid; q2 < 2048; q2 += 512) {
            int r = q2 >> 5, c4 = q2 & 31;
            *(float4*)&s_x[r][c4 * 4] =
                *(const float4*)(X + ((size_t)b * NPG + cb * 64 + r) * HDIM + c4 * 4);
        }
        for (int q2 = tid; q2 < 2048; q2 += 512) {
            int r = q2 >> 5, c = q2 & 31;
            float v = xs[((size_t)b * NPG + cb * 64 + r) * 32 + c];
            s_p[r][c] = __expf(v - s_m[c]) * s_i[c];
        }
        __syncthreads();
        int n0 = q * 16;
#pragma unroll 4
        for (int n = 0; n < 16; n++) {
            const ulonglong2* pr = (const ulonglong2*)&s_p[n0 + n][0];
            ulonglong2 u0 = pr[0], u1 = pr[1], u2 = pr[2], u3 = pr[3];
            ulonglong2 u4 = pr[4], u5 = pr[5], u6 = pr[6], u7 = pr[7];
            unsigned long long pd[16] = {u0.x, u0.y, u1.x, u1.y,
                                         u2.x, u2.y, u3.x, u3.y,
                                         u4.x, u4.y, u5.x, u5.y,
                                         u6.x, u6.y, u7.x, u7.y};
            unsigned long long xv = dup2(s_x[n0 + n][d]);
#pragma unroll
            for (int i = 0; i < 16; i++)
                asm("fma.rn.f32x2 %0, %1, %2, %0;"
                    : "+l"(acc2[i]) : "l"(xv), "l"(pd[i]));
        }
    }
    __syncthreads();
    float* P0 = &s_x[0][0];
    float* P1 = &s_x[32][0];
    if (q >= 2) {
        float* P = (q == 2) ? P0 : P1;
#pragma unroll
        for (int i = 0; i < 16; i++) {
            float f0, f1;
            asm("mov.b64 {%0,%1}, %2;" : "=f"(f0), "=f"(f1) : "l"(acc2[i]));
            P[(2 * i) * 128 + d]     = f0;
            P[(2 * i + 1) * 128 + d] = f1;
        }
    }
    __syncthreads();
    if (q < 2) {
        float* P = (q == 0) ? P0 : P1;
#pragma unroll
        for (int i = 0; i < 16; i++) {
            float f0, f1;
            asm("mov.b64 {%0,%1}, %2;" : "=f"(f0), "=f"(f1) : "l"(acc2[i]));
            P[(2 * i) * 128 + d]     += f0;
            P[(2 * i + 1) * 128 + d] += f1;
        }
    }
    __syncthreads();
    if (q < 2) {
#pragma unroll
        for (int c = 0; c < 16; c++) {
            int cc = q * 16 + c;
            P0[cc * 128 + d] += P1[cc * 128 + d];
        }
    }
    __syncthreads();

    {
        int j = tid & 127, tg = tid >> 7;
        float o0 = tb[j], o1 = o0;
        for (int k = 0; k < 512; k += 4) {
            float wv0 = W2[(k + 0) * 128 + j];
            float wv1 = W2[(k + 1) * 128 + j];
            float wv2 = W2[(k + 2) * 128 + j];
            float wv3 = W2[(k + 3) * 128 + j];
            int h = k >> 7, dk = k & 127;
            const float* y0 = &P0[((h << 3) + tg * 2) * 128 + dk];
            const float* y1 = &P0[((h << 3) + tg * 2 + 1) * 128 + dk];
            float4 v0 = *(const float4*)y0;
            float4 v1 = *(const float4*)y1;
            o0 += v0.x * wv0 + v0.y * wv1 + v0.z * wv2 + v0.w * wv3;
            o1 += v1.x * wv0 + v1.y * wv1 + v1.z * wv2 + v1.w * wv3;
        }
        tok[((size_t)b * NTOK + tg * 2) * HDIM + j]     = o0;
        tok[((size_t)b * NTOK + tg * 2 + 1) * HDIM + j] = o1;
    }
}

// ---------------- whole Mamba block per sequence (128 blocks) --------------
__device__ __forceinline__ float siluf(float v) { return v / (1.0f + expf(-v)); }

__global__ __launch_bounds__(256) void mamba_kernel(
    const float* __restrict__ tok,
    const float* __restrict__ in_w,  const float* __restrict__ conv_w,
    const float* __restrict__ conv_b,const float* __restrict__ x_w,
    const float* __restrict__ dt_w,  const float* __restrict__ dt_b,
    const float* __restrict__ A_log, const float* __restrict__ Dp,
    const float* __restrict__ out_w, const float* __restrict__ norm_w,
    const float* __restrict__ normf_w, float* __restrict__ gf)
{
    __shared__ float s_res[NTOK][HDIM];
    __shared__ float s_h  [NTOK][HDIM];
    __shared__ float s_u  [NTOK][MI];
    __shared__ float s_gt [NTOK][MI];
    __shared__ float s_dt [NTOK][MI];
    __shared__ float s_ssm[NTOK][MR + 2 * MS];
    __shared__ float s_y  [NTOK][MI];
    int b = blockIdx.x, tid = threadIdx.x;

    for (int idx = tid; idx < NTOK * HDIM; idx += 256)
        s_res[idx >> 7][idx & 127] = tok[b * NTOK * HDIM + idx];
    __syncthreads();
    {
        int t = tid >> 5, lane = tid & 31;
        float ss = 0.f;
        for (int j = lane; j < HDIM; j += 32) { float v = s_res[t][j]; ss += v * v; }
#pragma unroll
        for (int o = 16; o > 0; o >>= 1) ss += __shfl_xor_sync(~0u, ss, o);
        float rs = rsqrtf(ss * (1.0f / HDIM) + 1e-5f);
        for (int j = lane; j < HDIM; j += 32) s_h[t][j] = s_res[t][j] * rs * norm_w[j];
    }
    __syncthreads();
    {
        float accA[NTOK], accB[NTOK];
#pragma unroll
        for (int t = 0; t < NTOK; t++) { accA[t] = 0.f; accB[t] = 0.f; }
        const float* wp = in_w + tid;
#pragma unroll 4
        for (int k = 0; k < HDIM; k++) {
            float w0 = wp[k * 512];
            float w1 = wp[k * 512 + 256];
#pragma unroll
            for (int t = 0; t < NTOK; t++) {
                float h = s_h[t][k];
                accA[t] += h * w0;
                accB[t] += h * w1;
            }
        }
#pragma unroll
        for (int t = 0; t < NTOK; t++) {
            s_u[t][tid] = accA[t];
            s_gt[t][tid] = accB[t];
        }
    }
    __syncthreads();
    {
        int i = tid;
        float cw[MK];
#pragma unroll
        for (int k = 0; k < MK; k++) cw[k] = conv_w[i * MK + k];
        float cb = conv_b[i];
        float uv[NTOK];
#pragma unroll
        for (int t = 0; t < NTOK; t++) uv[t] = s_u[t][i];
#pragma unroll
        for (int t = NTOK - 1; t >= 0; t--) {
            float v = cb;
#pragma unroll
            for (int k = 0; k < MK; k++) {
                int tt = t + k - (MK - 1);
                if (tt >= 0) v += cw[k] * uv[tt];
            }
            uv[t] = siluf(v);
        }
#pragma unroll
        for (int t = 0; t < NTOK; t++) s_u[t][i] = uv[t];
    }
    __syncthreads();
    for (int idx = tid; idx < NTOK * (MR + 2 * MS); idx += 256) {
        int t = idx / 40, c = idx % 40;
        float acc = 0.f;
#pragma unroll 8
        for (int i = 0; i < MI; i++) acc += s_u[t][i] * x_w[i * 40 + c];
        s_ssm[t][c] = acc;
    }
    __syncthreads();
    for (int idx = tid; idx < NTOK * MI; idx += 256) {
        int t = idx >> 8, i = idx & 255;
        float acc = dt_b[i];
#pragma unroll
        for (int r = 0; r < MR; r++) acc += s_ssm[t][r] * dt_w[r * MI + i];
        s_dt[t][i] = fmaxf(acc, 0.f) + log1pf(expf(-fabsf(acc)));
    }
    __syncthreads();
    {
        int i = tid;
        float st[MS], Ar[MS];
#pragma unroll
        for (int s = 0; s < MS; s++) { st[s] = 0.f; Ar[s] = -expf(A_log[i * MS + s]); }
        float Dv = Dp[i];
#pragma unroll
        for (int t = 0; t < NTOK; t++) {
            float dtv = s_dt[t][i], uv = s_u[t][i];
            float y = 0.f;
#pragma unroll
            for (int s = 0; s < MS; s++) {
                float dA = expf(dtv * Ar[s]);
                st[s] = dA * st[s] + dtv * s_ssm[t][MR + s] * uv;
                y += st[s] * s_ssm[t][MR + MS + s];
            }
            y += uv * Dv;
            y *= siluf(s_gt[t][i]);
            s_y[t][i] = y;
        }
    }
    __syncthreads();
    {
        int j = tid & 127, t2 = tid >> 7;
        float acc[4] = {0.f, 0.f, 0.f, 0.f};
        const float* wp = out_w + j;
#pragma unroll 8
        for (int i = 0; i < MI; i++) {
            float w = wp[i * 128];
#pragma unroll
            for (int q = 0; q < 4; q++) acc[q] += s_y[t2 + 2 * q][i] * w;
        }
#pragma unroll
        for (int q = 0; q < 4; q++) {
            int t = t2 + 2 * q;
            s_h[t][j] = s_res[t][j] + acc[q];
        }
    }
    __syncthreads();
    {
        int t = tid >> 5, lane = tid & 31;
        float ss = 0.f;
        for (int j = lane; j < HDIM; j += 32) { float v = s_h[t][j]; ss += v * v; }
#pragma unroll
        for (int o = 16; o > 0; o >>= 1) ss += __shfl_xor_sync(~0u, ss, o);
        float rs = rsqrtf(ss * (1.0f / HDIM) + 1e-5f);
        for (int j = lane; j < HDIM; j += 32) s_h[t][j] = s_h[t][j] * rs * normf_w[j];
    }
    __syncthreads();
    for (int j = tid; j < HDIM; j += 256) {
        float acc = 0.f;
#pragma unroll
        for (int t = 0; t < NTOK; t++) acc += s_h[t][j];
        gf[b * HDIM + j] = acc * 0.125f;
    }
}

// ---------------- host driver ----------------------------------------------
extern "C" void kernel_launch(void* const* d_in, const int* in_sizes, int n_in,
                              void* d_out, int out_size)
{
    const float* x_in    = (const float*)d_in[0];
    const int*   ei      = (const int*)  d_in[1];
    const float* w_in    = (const float*)d_in[5];
    const float* b_in    = (const float*)d_in[6];
    const float* gin_w   = (const float*)d_in[7];
    const float* gin_b   = (const float*)d_in[8];
    const float* vt      = (const float*)d_in[9];
    const float* qkv_w   = (const float*)d_in[10];
    const float* qkv_b   = (const float*)d_in[11];
    const float* ao_w    = (const float*)d_in[12];
    const float* ao_b    = (const float*)d_in[13];
    const float* m_in_w  = (const float*)d_in[14];
    const float* m_conv_w= (const float*)d_in[15];
    const float* m_conv_b= (const float*)d_in[16];
    const float* m_x_w   = (const float*)d_in[17];
    const float* m_dt_w  = (const float*)d_in[18];
    const float* m_dt_b  = (const float*)d_in[19];
    const float* m_A_log = (const float*)d_in[20];
    const float* m_D     = (const float*)d_in[21];
    const float* m_out_w = (const float*)d_in[22];
    const float* m_norm_w  = (const float*)d_in[23];
    const float* m_normf_w = (const float*)d_in[24];
    const float* w_out   = (const float*)d_in[25];
    const float* b_out   = (const float*)d_in[26];

    const int N = in_sizes[0] / HDIM;
    const int E = in_sizes[1] / 2;

    float *xa, *xcur, *xs, *Mb, *W2, *tb, *tk, *gf, *S;
    int *deg, *off, *cur, *bsum, *ssrc;
    cudaGetSymbolAddress((void**)&xa,   g_xa);
    cudaGetSymbolAddress((void**)&xcur, g_xcur);
    cudaGetSymbolAddress((void**)&xs,   g_xs);
    cudaGetSymbolAddress((void**)&Mb,   g_M);
    cudaGetSymbolAddress((void**)&W2,   g_W2);
    cudaGetSymbolAddress((void**)&tb,   g_tb);
    cudaGetSymbolAddress((void**)&tk,   g_tok);
    cudaGetSymbolAddress((void**)&gf,   g_gf);
    cudaGetSymbolAddress((void**)&S,    g_S);
    cudaGetSymbolAddress((void**)&deg,  g_deg);
    cudaGetSymbolAddress((void**)&off,  g_off);
    cudaGetSymbolAddress((void**)&cur,  g_cur);
    cudaGetSymbolAddress((void**)&bsum, g_bsum);
    cudaGetSymbolAddress((void**)&ssrc, g_ssrc);

    cudaFuncSetAttribute(gemm_t,
                         cudaFuncAttributeMaxDynamicSharedMemorySize, GEMM_SMEM);

    cudaStream_t s2;
    cudaStreamCreateWithFlags(&s2, cudaStreamNonBlocking);
    cudaEvent_t evF, evJ;
    cudaEventCreateWithFlags(&evF, cudaEventDisableTiming);
    cudaEventCreateWithFlags(&evJ, cudaEventDisableTiming);

    // ---- CSR build (parallel scan); S memset hoisted ----
    cudaMemsetAsync(S, 0, NGRAPH * HDIM * sizeof(float));
    cudaMemsetAsync(deg, 0, (size_t)N * sizeof(int));

    // fork s2 from the capturing stream BEFORE any work lands on it
    cudaEventRecord(evF, 0);
    cudaStreamWaitEvent(s2, evF, 0);

    const int E2 = E / 2;
    hist_kernel<<<(E2 + 255) / 256, 256>>>((const int2*)(ei + E), E2, deg);
    blocksum_kernel<<<512, 256>>>(deg, bsum);
    scanb_kernel<<<1, 512>>>(bsum);
    offsets_kernel<<<512, 256>>>(deg, bsum, off, cur);
    scatter_kernel<<<(E2 + 255) / 256, 256>>>((const int2*)ei, (const int2*)(ei + E),
                                              E2, cur, ssrc);

    // ---- per-layer weight precompute (both layers) on forked side stream --
    for (int l = 0; l < 2; l++) {
        const float* qkvw_l = qkv_w + (size_t)l * 128 * 384;
        const float* qkvb_l = qkv_b + l * 384;
        const float* aow_l  = ao_w + (size_t)l * 128 * 128;
        wstack_kern<<<256, 256, 0, s2>>>(qkvw_l, aow_l, W2 + (size_t)l * 4 * HDIM * HDIM);
        precomp_kernel<<<1, 256, 0, s2>>>(vt + (size_t)l * NTOK * 128,
                                          qkvw_l, qkvb_l, aow_l, ao_b + l * 128,
                                          Mb + (size_t)l * HDIM * 32, tb + l * HDIM);
    }
    cudaEventRecord(evJ, s2);
    cudaStreamWaitEvent(0, evJ, 0);

    const int aggBlocks = N / 8;
    const dim3 gemmGridN(N / 128, 1);

    // x = gin(x_in) — with fused xs for layer 0
    csr_agg_kernel<<<aggBlocks, 256>>>(x_in, off, ssrc, xa);
    gemm_t<<<gemmGridN, 256, GEMM_SMEM>>>(xa, w_in, 128, b_in, 1.f, nullptr,
                                          xcur, Mb, xs);

    for (int l = 0; l < 2; l++) {
        // fork: csr_agg(xcur) on side stream
        cudaEventRecord(evF, 0);
        cudaStreamWaitEvent(s2, evF, 0);
        csr_agg_kernel<<<aggBlocks, 256, 0, s2>>>(xcur, off, ssrc, xa);
        cudaEventRecord(evJ, s2);

        // main stream: attention + mamba (read xcur/xs)
        attn3_kernel<<<NGRAPH, 512>>>(xs, xcur, W2 + (size_t)l * 4 * HDIM * HDIM,
                                      tb + l * HDIM, tk);
        mamba_kernel<<<NGRAPH, 256>>>(tk, m_in_w, m_conv_w, m_conv_b, m_x_w,
                                      m_dt_w, m_dt_b, m_A_log, m_D, m_out_w,
                                      m_norm_w, m_normf_w, gf);

        // join, GIN GEMM (+ fused xs for next layer if any)
        cudaStreamWaitEvent(0, evJ, 0);
        const float* Mn = (l == 0) ? Mb + (size_t)HDIM * 32 : nullptr;
        float* xsn = (l == 0) ? xs : nullptr;
        gemm_t<<<gemmGridN, 256, GEMM_SMEM>>>(xa, gin_w + (size_t)l * 128 * 128, 128,
                                              gin_b + l * 128, 1.f, gf, xcur,
                                              Mn, xsn);
    }

    // final: out = (sum_g (x+agg)) @ w_out + 1024*b_out
    csr_sum_kernel<<<N / 8, 256>>>(xcur, off, ssrc, S);
    gemm_t<<<dim3(1, 1), 256, GEMM_SMEM>>>(S, w_out, 128, b_out, 1024.f, nullptr,
                                           (float*)d_out, nullptr, nullptr);

    cudaEventDestroy(evF);
    cudaEventDestroy(evJ);
    cudaStreamDestroy(s2);
}